// round 1
// baseline (speedup 1.0000x reference)
#include <cuda_runtime.h>
#include <math.h>

#define NB 8
#define CDIM 128
#define HH 192
#define WW 192
#define HWD (HH*WW)          // 36864
#define PTOT (NB*HWD)        // 294912
#define LROW 192
#define NROWS (NB*HH)        // 1536 (== NB*WW)
#define BN_EPS 1e-5f

// ---------------- device scratch (allocation-free: module-load globals) ----------------
__device__ float g_th [PTOT*CDIM];   // theta (NHWC), later reused as u = f_h
__device__ float g_ph [PTOT*CDIM];   // phi   (NHWC), later reused as v = f_v
__device__ float g_g  [PTOT*CDIM];   // g     (NHWC), later reused as final NHWC tmp
__device__ float g_sch[PTOT*CDIM];   // horizontal shortcut (BN, no relu)
__device__ float g_scv[PTOT*CDIM];   // vertical shortcut
__device__ float g_ah [PTOT*CDIM];   // horizontal attention out
__device__ float g_av [PTOT*CDIM];   // vertical attention out

__device__ float g_Wall[CDIM*640];   // folded weights for stage A: cols = [theta|phi|g|sc_h|sc_v]
__device__ float g_biasA[640];
__device__ float g_W3[CDIM*CDIM];    // folded W7[3]
__device__ float g_b3[CDIM];
__device__ float g_W5[CDIM*CDIM];    // folded W7[5]
__device__ float g_b5[CDIM];
__device__ float g_Wa[2*CDIM*CDIM];  // folded Wa
__device__ float g_ba[CDIM];

// ---------------- BN folding prep ----------------
__global__ void prep_kernel(const float* __restrict__ W7, const float* __restrict__ m7,
                            const float* __restrict__ v7, const float* __restrict__ b7,
                            const float* __restrict__ Wa, const float* __restrict__ ma,
                            const float* __restrict__ va, const float* __restrict__ ba) {
    int t = blockIdx.x * blockDim.x + threadIdx.x;
    int stride = gridDim.x * blockDim.x;
    const int mats[5] = {0, 1, 2, 4, 6};
    // stage A folded weights
    for (int idx = t; idx < 128*640; idx += stride) {
        int k = idx / 640, j = idx % 640;
        int mi = j >> 7, d = j & 127;
        int m = mats[mi];
        float rs = rsqrtf(v7[m*128 + d] + BN_EPS);
        g_Wall[idx] = W7[(m*128 + k)*128 + d] * rs;
        if (k == 0) g_biasA[j] = b7[m*128 + d] - m7[m*128 + d]*rs;
    }
    // W3 / W5 folded
    for (int idx = t; idx < 128*128; idx += stride) {
        int k = idx >> 7, d = idx & 127;
        float rs3 = rsqrtf(v7[3*128 + d] + BN_EPS);
        float rs5 = rsqrtf(v7[5*128 + d] + BN_EPS);
        g_W3[idx] = W7[(3*128 + k)*128 + d] * rs3;
        g_W5[idx] = W7[(5*128 + k)*128 + d] * rs5;
        if (k == 0) {
            g_b3[d] = b7[3*128 + d] - m7[3*128 + d]*rs3;
            g_b5[d] = b7[5*128 + d] - m7[5*128 + d]*rs5;
        }
    }
    // Wa folded
    for (int idx = t; idx < 256*128; idx += stride) {
        int k = idx >> 7, d = idx & 127;
        float rs = rsqrtf(va[d] + BN_EPS);
        g_Wa[idx] = Wa[idx] * rs;
        if (k == 0) g_ba[d] = ba[d] - ma[d]*rs;
    }
}

// ---------------- generic 128x128x16 tiled GEMM ----------------
// MODE 0: stage A.  X = f_common (NCHW).  W = g_Wall (ld 640), col block = blockIdx.y (mat).
//         out[mat] in {g_th,g_ph,g_g,g_sch,g_scv}; relu for mat<3.
// MODE 1: C1.  sel = blockIdx.y. X = (sel? g_av : g_ah) row-major 128.
//         W = sel? g_W5 : g_W3.  add = sel? g_scv : g_sch. relu. out = sel? g_ph : g_th.
// MODE 2: C2.  K=256, X chunks from g_th (k<128) / g_ph. W = g_Wa. relu. out = g_g (NHWC tmp).
template<int MODE>
__global__ __launch_bounds__(256, 2) void gemm_kernel(const float* __restrict__ X) {
    __shared__ float Xs[16][132];
    __shared__ float Ws[16][128];
    const int tid = threadIdx.x;
    const int p0 = blockIdx.x * 128;
    const int ty = tid >> 4, tx = tid & 15;
    const int r0 = ty * 8, c0 = tx * 8;

    float acc[8][8];
#pragma unroll
    for (int i = 0; i < 8; i++)
#pragma unroll
        for (int j = 0; j < 8; j++) acc[i][j] = 0.f;

    const int KTOT = (MODE == 2) ? 256 : 128;
    const float* Wp; int ldw; int wcol0;
    const float* xin = nullptr;
    if (MODE == 0) { Wp = g_Wall; ldw = 640; wcol0 = blockIdx.y * 128; }
    else if (MODE == 1) {
        Wp = blockIdx.y ? g_W5 : g_W3; ldw = 128; wcol0 = 0;
        xin = blockIdx.y ? g_av : g_ah;
    } else { Wp = g_Wa; ldw = 128; wcol0 = 0; }

    for (int k0 = 0; k0 < KTOT; k0 += 16) {
        if (MODE == 0) {
            // NCHW source: addr = n*C*HW + k*HW + hw
            int n = p0 / HWD, hw0 = p0 % HWD;
            const float* src = X + (size_t)n*CDIM*HWD + (size_t)k0*HWD + hw0;
#pragma unroll
            for (int i = 0; i < 8; i++) {
                int idx = tid + i*256;
                int k = idx >> 7, pl = idx & 127;
                Xs[k][pl] = src[(size_t)k*HWD + pl];
            }
        } else {
            const float* src;
            if (MODE == 1) src = xin + (size_t)p0*128 + k0;
            else           src = ((k0 < 128) ? g_th : g_ph) + (size_t)p0*128 + (k0 & 127);
#pragma unroll
            for (int i = 0; i < 2; i++) {
                int id = tid + i*256;          // 512 float4
                int pl = id >> 2, kq = id & 3;
                float4 v = *(const float4*)(src + (size_t)pl*128 + kq*4);
                Xs[kq*4+0][pl] = v.x; Xs[kq*4+1][pl] = v.y;
                Xs[kq*4+2][pl] = v.z; Xs[kq*4+3][pl] = v.w;
            }
        }
#pragma unroll
        for (int i = 0; i < 8; i++) {
            int idx = tid + i*256;
            int k = idx >> 7, c = idx & 127;
            Ws[k][c] = Wp[(size_t)(k0 + k)*ldw + wcol0 + c];
        }
        __syncthreads();
#pragma unroll
        for (int kk = 0; kk < 16; kk++) {
            float a[8], b[8];
            float4 t0 = *(const float4*)&Xs[kk][r0];
            float4 t1 = *(const float4*)&Xs[kk][r0+4];
            a[0]=t0.x; a[1]=t0.y; a[2]=t0.z; a[3]=t0.w;
            a[4]=t1.x; a[5]=t1.y; a[6]=t1.z; a[7]=t1.w;
            float4 u0 = *(const float4*)&Ws[kk][c0];
            float4 u1 = *(const float4*)&Ws[kk][c0+4];
            b[0]=u0.x; b[1]=u0.y; b[2]=u0.z; b[3]=u0.w;
            b[4]=u1.x; b[5]=u1.y; b[6]=u1.z; b[7]=u1.w;
#pragma unroll
            for (int i = 0; i < 8; i++)
#pragma unroll
                for (int j = 0; j < 8; j++)
                    acc[i][j] = fmaf(a[i], b[j], acc[i][j]);
        }
        __syncthreads();
    }

    // epilogue
    float* outp; const float* biasp; const float* addp = nullptr; bool relu;
    if (MODE == 0) {
        int mat = blockIdx.y;
        outp = (mat==0) ? g_th : (mat==1) ? g_ph : (mat==2) ? g_g : (mat==3) ? g_sch : g_scv;
        biasp = g_biasA + mat*128;
        relu = (mat < 3);
    } else if (MODE == 1) {
        outp = blockIdx.y ? g_ph : g_th;
        biasp = blockIdx.y ? g_b5 : g_b3;
        addp  = blockIdx.y ? g_scv : g_sch;
        relu = true;
    } else { outp = g_g; biasp = g_ba; relu = true; }

    float bj[8];
#pragma unroll
    for (int j = 0; j < 8; j++) bj[j] = biasp[c0 + j];

#pragma unroll
    for (int i = 0; i < 8; i++) {
        size_t ro = (size_t)(p0 + r0 + i)*128 + c0;
        float r[8];
#pragma unroll
        for (int j = 0; j < 8; j++) r[j] = acc[i][j] + bj[j];
        if (MODE == 1) {
            float4 a0 = *(const float4*)(addp + ro);
            float4 a1 = *(const float4*)(addp + ro + 4);
            r[0]+=a0.x; r[1]+=a0.y; r[2]+=a0.z; r[3]+=a0.w;
            r[4]+=a1.x; r[5]+=a1.y; r[6]+=a1.z; r[7]+=a1.w;
        }
        if (relu) {
#pragma unroll
            for (int j = 0; j < 8; j++) r[j] = fmaxf(r[j], 0.f);
        }
        float4 s0 = make_float4(r[0],r[1],r[2],r[3]);
        float4 s1 = make_float4(r[4],r[5],r[6],r[7]);
        *(float4*)(outp + ro)     = s0;
        *(float4*)(outp + ro + 4) = s1;
    }
}

// ---------------- axial attention (flash-style, fp32) ----------------
// grid = (L/64, 1536, 2).  dir 0: horizontal rows (stride C); dir 1: vertical (stride W*C)
__global__ __launch_bounds__(256, 1) void attn_kernel() {
    extern __shared__ float sm[];
    float* Qs = sm;                 // [128][68] c-major
    float* Ks = Qs + 128*68;        // [128][68] c-major
    float* Vs = Ks + 128*68;        // [64][132] row-major
    float* Ps = Vs + 64*132;        // [64][68]
    float* red_alpha = Ps + 64*68;  // [64]
    float* red_l = red_alpha + 64;  // [64]

    const int tid = threadIdx.x;
    const int q0 = blockIdx.x * 64;
    const int row = blockIdx.y;
    const int dir = blockIdx.z;

    size_t base; int stride;
    if (dir == 0) { base = (size_t)row * LROW * CDIM; stride = CDIM; }
    else {
        int n = row / WW, w = row % WW;
        base = (size_t)n*HH*WW*CDIM + (size_t)w*CDIM;
        stride = WW*CDIM;
    }
    const float* thp = g_th + base;
    const float* php = g_ph + base;
    const float* gp  = g_g  + base;
    float* outp = (dir == 0 ? g_ah : g_av) + base;

    // load Q [64][128] transposed into Qs[c][i]
#pragma unroll
    for (int t = 0; t < 8; t++) {
        int id = tid + t*256;            // 2048 float4
        int i = id >> 5, cq = (id & 31)*4;
        float4 v = *(const float4*)(thp + (size_t)(q0 + i)*stride + cq);
        Qs[(cq+0)*68 + i] = v.x; Qs[(cq+1)*68 + i] = v.y;
        Qs[(cq+2)*68 + i] = v.z; Qs[(cq+3)*68 + i] = v.w;
    }

    const int ty = tid >> 4, tx = tid & 15;
    const int i0 = ty*4, j0 = tx*4, cc0 = tx*8;
    const int grow = tid >> 2, lane = tid & 3;

    float o[4][8];
#pragma unroll
    for (int i = 0; i < 4; i++)
#pragma unroll
        for (int j = 0; j < 8; j++) o[i][j] = 0.f;
    float m_run = -1e30f, l_run = 0.f;
    const float scale = 0.08838834764831845f;  // 1/sqrt(128)

    for (int kb = 0; kb < LROW; kb += 64) {
        // K chunk transposed, V chunk row-major
#pragma unroll
        for (int t = 0; t < 8; t++) {
            int id = tid + t*256;
            int j = id >> 5, cq = (id & 31)*4;
            float4 v = *(const float4*)(php + (size_t)(kb + j)*stride + cq);
            Ks[(cq+0)*68 + j] = v.x; Ks[(cq+1)*68 + j] = v.y;
            Ks[(cq+2)*68 + j] = v.z; Ks[(cq+3)*68 + j] = v.w;
        }
#pragma unroll
        for (int t = 0; t < 8; t++) {
            int id = tid + t*256;
            int j = id >> 5, cq = (id & 31)*4;
            *(float4*)&Vs[j*132 + cq] = *(const float4*)(gp + (size_t)(kb + j)*stride + cq);
        }
        __syncthreads();

        // S[64][64] = Q K^T * scale
        float s[4][4];
#pragma unroll
        for (int i = 0; i < 4; i++)
#pragma unroll
            for (int j = 0; j < 4; j++) s[i][j] = 0.f;
#pragma unroll 8
        for (int c = 0; c < CDIM; c++) {
            float4 q4 = *(const float4*)&Qs[c*68 + i0];
            float4 k4 = *(const float4*)&Ks[c*68 + j0];
            float aq[4] = {q4.x, q4.y, q4.z, q4.w};
            float bk[4] = {k4.x, k4.y, k4.z, k4.w};
#pragma unroll
            for (int i = 0; i < 4; i++)
#pragma unroll
                for (int j = 0; j < 4; j++)
                    s[i][j] = fmaf(aq[i], bk[j], s[i][j]);
        }
#pragma unroll
        for (int i = 0; i < 4; i++) {
            float4 pv = make_float4(s[i][0]*scale, s[i][1]*scale, s[i][2]*scale, s[i][3]*scale);
            *(float4*)&Ps[(i0 + i)*68 + j0] = pv;
        }
        __syncthreads();

        // online softmax per row (4 threads/row)
        float mx = -1e30f;
#pragma unroll
        for (int jj = 0; jj < 16; jj++)
            mx = fmaxf(mx, Ps[grow*68 + jj*4 + lane]);
        mx = fmaxf(mx, __shfl_xor_sync(0xffffffffu, mx, 1));
        mx = fmaxf(mx, __shfl_xor_sync(0xffffffffu, mx, 2));
        float m_new = fmaxf(m_run, mx);
        float alpha = __expf(m_run - m_new);
        float ssum = 0.f;
#pragma unroll
        for (int jj = 0; jj < 16; jj++) {
            int idx = grow*68 + jj*4 + lane;
            float e = __expf(Ps[idx] - m_new);
            Ps[idx] = e;
            ssum += e;
        }
        ssum += __shfl_xor_sync(0xffffffffu, ssum, 1);
        ssum += __shfl_xor_sync(0xffffffffu, ssum, 2);
        l_run = l_run * alpha + ssum;
        m_run = m_new;
        if (lane == 0) red_alpha[grow] = alpha;
        __syncthreads();

        // O = O*alpha + P V
        float al[4];
#pragma unroll
        for (int i = 0; i < 4; i++) al[i] = red_alpha[i0 + i];
#pragma unroll
        for (int i = 0; i < 4; i++)
#pragma unroll
            for (int j = 0; j < 8; j++) o[i][j] *= al[i];
#pragma unroll 4
        for (int j = 0; j < 64; j++) {
            float4 v0 = *(const float4*)&Vs[j*132 + cc0];
            float4 v1 = *(const float4*)&Vs[j*132 + cc0 + 4];
            float vv[8] = {v0.x, v0.y, v0.z, v0.w, v1.x, v1.y, v1.z, v1.w};
            float pp[4];
#pragma unroll
            for (int i = 0; i < 4; i++) pp[i] = Ps[(i0 + i)*68 + j];
#pragma unroll
            for (int i = 0; i < 4; i++)
#pragma unroll
                for (int jj = 0; jj < 8; jj++)
                    o[i][jj] = fmaf(pp[i], vv[jj], o[i][jj]);
        }
        __syncthreads();
    }

    if (lane == 0) red_l[grow] = l_run;
    __syncthreads();
#pragma unroll
    for (int i = 0; i < 4; i++) {
        float inv = 1.f / red_l[i0 + i];
        float4 s0 = make_float4(o[i][0]*inv, o[i][1]*inv, o[i][2]*inv, o[i][3]*inv);
        float4 s1 = make_float4(o[i][4]*inv, o[i][5]*inv, o[i][6]*inv, o[i][7]*inv);
        float* dst = outp + (size_t)(q0 + i0 + i)*stride + cc0;
        *(float4*)dst = s0;
        *(float4*)(dst + 4) = s1;
    }
}

// ---------------- NHWC -> NCHW output transpose ----------------
__global__ void transpose_out(float* __restrict__ out) {
    __shared__ float tile[32][33];
    int n = blockIdx.z;
    int hw0 = blockIdx.x * 32;
    int c0 = blockIdx.y * 32;
    int tx = threadIdx.x, ty = threadIdx.y;
    const float* src = g_g + (size_t)n*HWD*CDIM;
#pragma unroll
    for (int i = 0; i < 32; i += 8)
        tile[ty + i][tx] = src[(size_t)(hw0 + ty + i)*CDIM + c0 + tx];
    __syncthreads();
    float* dst = out + (size_t)n*CDIM*HWD;
#pragma unroll
    for (int i = 0; i < 32; i += 8)
        dst[(size_t)(c0 + ty + i)*HWD + hw0 + tx] = tile[tx][ty + i];
}

// ---------------- launch ----------------
extern "C" void kernel_launch(void* const* d_in, const int* in_sizes, int n_in,
                              void* d_out, int out_size) {
    const float* f  = (const float*)d_in[0];
    const float* W7 = (const float*)d_in[1];
    const float* m7 = (const float*)d_in[2];
    const float* v7 = (const float*)d_in[3];
    const float* b7 = (const float*)d_in[4];
    const float* Wa = (const float*)d_in[5];
    const float* ma = (const float*)d_in[6];
    const float* va = (const float*)d_in[7];
    const float* ba = (const float*)d_in[8];
    float* out = (float*)d_out;

    prep_kernel<<<64, 256>>>(W7, m7, v7, b7, Wa, ma, va, ba);

    // stage A: theta, phi, g, sc_h, sc_v
    gemm_kernel<0><<<dim3(PTOT/128, 5), 256>>>(f);

    // axial attention, both directions
    int smem_bytes = (128*68 + 128*68 + 64*132 + 64*68 + 128) * 4;
    cudaFuncSetAttribute(attn_kernel, cudaFuncAttributeMaxDynamicSharedMemorySize, smem_bytes);
    attn_kernel<<<dim3(LROW/64, NROWS, 2), 256, smem_bytes>>>();

    // C1: u = relu(ah*W3 + b3 + sc_h) -> g_th ; v = relu(av*W5 + b5 + sc_v) -> g_ph
    gemm_kernel<1><<<dim3(PTOT/128, 2), 256>>>(nullptr);

    // C2: final conv over concat(u, v) -> g_g (NHWC tmp)
    gemm_kernel<2><<<dim3(PTOT/128, 1), 256>>>(nullptr);

    // NHWC -> NCHW
    transpose_out<<<dim3(HWD/32, CDIM/32, NB), dim3(32, 8)>>>(out);
}

// round 3
// speedup vs baseline: 1.0100x; 1.0100x over previous
#include <cuda_runtime.h>
#include <math.h>
#include <cstdint>

#define NB 8
#define CDIM 128
#define HH 192
#define WW 192
#define HWD (HH*WW)          // 36864
#define PTOT (NB*HWD)        // 294912
#define LROW 192
#define NROWS (NB*HH)        // 1536
#define BN_EPS 1e-5f

typedef unsigned long long ull;

// ---------------- f32x2 packed-math helpers (family-portable PTX, sm_100+) ----------------
__device__ __forceinline__ ull pack2(float lo, float hi) {
    ull r;
    asm("mov.b64 %0, {%1, %2};" : "=l"(r) : "f"(lo), "f"(hi));
    return r;
}
__device__ __forceinline__ float2 unpack2(ull v) {
    float2 r;
    asm("mov.b64 {%0, %1}, %2;" : "=f"(r.x), "=f"(r.y) : "l"(v));
    return r;
}
__device__ __forceinline__ ull ffma2(ull a, ull b, ull c) {
    ull d;
    asm("fma.rn.f32x2 %0, %1, %2, %3;" : "=l"(d) : "l"(a), "l"(b), "l"(c));
    return d;
}
__device__ __forceinline__ ull fmul2(ull a, ull b) {
    ull d;
    asm("mul.rn.f32x2 %0, %1, %2;" : "=l"(d) : "l"(a), "l"(b));
    return d;
}

// ---------------- device scratch (allocation-free: module-load globals) ----------------
__device__ float g_th [PTOT*CDIM];   // theta (NHWC), later reused as u = f_h
__device__ float g_ph [PTOT*CDIM];   // phi   (NHWC), later reused as v = f_v
__device__ float g_g  [PTOT*CDIM];   // g     (NHWC), later reused as final NHWC tmp
__device__ float g_sch[PTOT*CDIM];   // horizontal shortcut (BN, no relu)
__device__ float g_scv[PTOT*CDIM];   // vertical shortcut
__device__ float g_ah [PTOT*CDIM];   // horizontal attention out
__device__ float g_av [PTOT*CDIM];   // vertical attention out

__device__ float g_Wall[CDIM*640];   // folded weights for stage A: cols = [theta|phi|g|sc_h|sc_v]
__device__ float g_biasA[640];
__device__ float g_W3[CDIM*CDIM];    // folded W7[3]
__device__ float g_b3[CDIM];
__device__ float g_W5[CDIM*CDIM];    // folded W7[5]
__device__ float g_b5[CDIM];
__device__ float g_Wa[2*CDIM*CDIM];  // folded Wa
__device__ float g_ba[CDIM];

// ---------------- BN folding prep ----------------
__global__ void prep_kernel(const float* __restrict__ W7, const float* __restrict__ m7,
                            const float* __restrict__ v7, const float* __restrict__ b7,
                            const float* __restrict__ Wa, const float* __restrict__ ma,
                            const float* __restrict__ va, const float* __restrict__ ba) {
    int t = blockIdx.x * blockDim.x + threadIdx.x;
    int stride = gridDim.x * blockDim.x;
    const int mats[5] = {0, 1, 2, 4, 6};
    for (int idx = t; idx < 128*640; idx += stride) {
        int k = idx / 640, j = idx % 640;
        int mi = j >> 7, d = j & 127;
        int m = mats[mi];
        float rs = rsqrtf(v7[m*128 + d] + BN_EPS);
        g_Wall[idx] = W7[(m*128 + k)*128 + d] * rs;
        if (k == 0) g_biasA[j] = b7[m*128 + d] - m7[m*128 + d]*rs;
    }
    for (int idx = t; idx < 128*128; idx += stride) {
        int k = idx >> 7, d = idx & 127;
        float rs3 = rsqrtf(v7[3*128 + d] + BN_EPS);
        float rs5 = rsqrtf(v7[5*128 + d] + BN_EPS);
        g_W3[idx] = W7[(3*128 + k)*128 + d] * rs3;
        g_W5[idx] = W7[(5*128 + k)*128 + d] * rs5;
        if (k == 0) {
            g_b3[d] = b7[3*128 + d] - m7[3*128 + d]*rs3;
            g_b5[d] = b7[5*128 + d] - m7[5*128 + d]*rs5;
        }
    }
    for (int idx = t; idx < 256*128; idx += stride) {
        int k = idx >> 7, d = idx & 127;
        float rs = rsqrtf(va[d] + BN_EPS);
        g_Wa[idx] = Wa[idx] * rs;
        if (k == 0) g_ba[d] = ba[d] - ma[d]*rs;
    }
}

// ---------------- generic 128x128x16 tiled GEMM (f32x2 packed inner loop) ----------------
template<int MODE>
__global__ __launch_bounds__(256, 2) void gemm_kernel(const float* __restrict__ X) {
    __shared__ float Xs[16][132];
    __shared__ float Ws[16][128];
    const int tid = threadIdx.x;
    const int p0 = blockIdx.x * 128;
    const int ty = tid >> 4, tx = tid & 15;
    const int r0 = ty * 8, c0 = tx * 8;

    // accumulators: [i][jp] pairs over j (adjacent output columns)
    ull acc2[8][4];
#pragma unroll
    for (int i = 0; i < 8; i++)
#pragma unroll
        for (int q = 0; q < 4; q++) acc2[i][q] = 0ull;

    const int KTOT = (MODE == 2) ? 256 : 128;
    const float* Wp; int ldw; int wcol0;
    const float* xin = nullptr;
    if (MODE == 0) { Wp = g_Wall; ldw = 640; wcol0 = blockIdx.y * 128; }
    else if (MODE == 1) {
        Wp = blockIdx.y ? g_W5 : g_W3; ldw = 128; wcol0 = 0;
        xin = blockIdx.y ? g_av : g_ah;
    } else { Wp = g_Wa; ldw = 128; wcol0 = 0; }

    for (int k0 = 0; k0 < KTOT; k0 += 16) {
        if (MODE == 0) {
            int n = p0 / HWD, hw0 = p0 % HWD;
            const float* src = X + (size_t)n*CDIM*HWD + (size_t)k0*HWD + hw0;
#pragma unroll
            for (int i = 0; i < 8; i++) {
                int idx = tid + i*256;
                int k = idx >> 7, pl = idx & 127;
                Xs[k][pl] = src[(size_t)k*HWD + pl];
            }
        } else {
            const float* src;
            if (MODE == 1) src = xin + (size_t)p0*128 + k0;
            else           src = ((k0 < 128) ? g_th : g_ph) + (size_t)p0*128 + (k0 & 127);
#pragma unroll
            for (int i = 0; i < 2; i++) {
                int id = tid + i*256;          // 512 float4
                int pl = id >> 2, kq = id & 3;
                float4 v = *(const float4*)(src + (size_t)pl*128 + kq*4);
                Xs[kq*4+0][pl] = v.x; Xs[kq*4+1][pl] = v.y;
                Xs[kq*4+2][pl] = v.z; Xs[kq*4+3][pl] = v.w;
            }
        }
#pragma unroll
        for (int i = 0; i < 8; i++) {
            int idx = tid + i*256;
            int k = idx >> 7, c = idx & 127;
            Ws[k][c] = Wp[(size_t)(k0 + k)*ldw + wcol0 + c];
        }
        __syncthreads();
#pragma unroll
        for (int kk = 0; kk < 16; kk++) {
            float a[8];
            float4 t0 = *(const float4*)&Xs[kk][r0];
            float4 t1 = *(const float4*)&Xs[kk][r0+4];
            a[0]=t0.x; a[1]=t0.y; a[2]=t0.z; a[3]=t0.w;
            a[4]=t1.x; a[5]=t1.y; a[6]=t1.z; a[7]=t1.w;
            // B pairs: adjacent columns, contiguous in smem -> direct b64 loads
            longlong2 u0 = *(const longlong2*)&Ws[kk][c0];
            longlong2 u1 = *(const longlong2*)&Ws[kk][c0+4];
            ull b2[4] = {(ull)u0.x, (ull)u0.y, (ull)u1.x, (ull)u1.y};
#pragma unroll
            for (int i = 0; i < 8; i++) {
                ull ad = pack2(a[i], a[i]);
#pragma unroll
                for (int q = 0; q < 4; q++)
                    acc2[i][q] = ffma2(ad, b2[q], acc2[i][q]);
            }
        }
        __syncthreads();
    }

    // epilogue
    float* outp; const float* biasp; const float* addp = nullptr; bool relu;
    if (MODE == 0) {
        int mat = blockIdx.y;
        outp = (mat==0) ? g_th : (mat==1) ? g_ph : (mat==2) ? g_g : (mat==3) ? g_sch : g_scv;
        biasp = g_biasA + mat*128;
        relu = (mat < 3);
    } else if (MODE == 1) {
        outp = blockIdx.y ? g_ph : g_th;
        biasp = blockIdx.y ? g_b5 : g_b3;
        addp  = blockIdx.y ? g_scv : g_sch;
        relu = true;
    } else { outp = g_g; biasp = g_ba; relu = true; }

    float bj[8];
#pragma unroll
    for (int j = 0; j < 8; j++) bj[j] = biasp[c0 + j];

#pragma unroll
    for (int i = 0; i < 8; i++) {
        size_t ro = (size_t)(p0 + r0 + i)*128 + c0;
        float r[8];
#pragma unroll
        for (int q = 0; q < 4; q++) {
            float2 u = unpack2(acc2[i][q]);
            r[q*2+0] = u.x + bj[q*2+0];
            r[q*2+1] = u.y + bj[q*2+1];
        }
        if (MODE == 1) {
            float4 a0 = *(const float4*)(addp + ro);
            float4 a1 = *(const float4*)(addp + ro + 4);
            r[0]+=a0.x; r[1]+=a0.y; r[2]+=a0.z; r[3]+=a0.w;
            r[4]+=a1.x; r[5]+=a1.y; r[6]+=a1.z; r[7]+=a1.w;
        }
        if (relu) {
#pragma unroll
            for (int j = 0; j < 8; j++) r[j] = fmaxf(r[j], 0.f);
        }
        float4 s0 = make_float4(r[0],r[1],r[2],r[3]);
        float4 s1 = make_float4(r[4],r[5],r[6],r[7]);
        *(float4*)(outp + ro)     = s0;
        *(float4*)(outp + ro + 4) = s1;
    }
}

// ---------------- axial attention (flash-style, fp32, f32x2 packed GEMM loops) ----------------
__global__ __launch_bounds__(256, 1) void attn_kernel() {
    extern __shared__ float sm[];
    float* Qs = sm;                 // [128][68] c-major
    float* Ks = Qs + 128*68;        // [128][68] c-major
    float* Vs = Ks + 128*68;        // [64][132] row-major
    float* Ps = Vs + 64*132;        // [64][68]
    float* red_alpha = Ps + 64*68;  // [64]
    float* red_l = red_alpha + 64;  // [64]

    const int tid = threadIdx.x;
    const int q0 = blockIdx.x * 64;
    const int row = blockIdx.y;
    const int dir = blockIdx.z;

    size_t base; int stride;
    if (dir == 0) { base = (size_t)row * LROW * CDIM; stride = CDIM; }
    else {
        int n = row / WW, w = row % WW;
        base = (size_t)n*HH*WW*CDIM + (size_t)w*CDIM;
        stride = WW*CDIM;
    }
    const float* thp = g_th + base;
    const float* php = g_ph + base;
    const float* gp  = g_g  + base;
    float* outp = (dir == 0 ? g_ah : g_av) + base;

#pragma unroll
    for (int t = 0; t < 8; t++) {
        int id = tid + t*256;            // 2048 float4
        int i = id >> 5, cq = (id & 31)*4;
        float4 v = *(const float4*)(thp + (size_t)(q0 + i)*stride + cq);
        Qs[(cq+0)*68 + i] = v.x; Qs[(cq+1)*68 + i] = v.y;
        Qs[(cq+2)*68 + i] = v.z; Qs[(cq+3)*68 + i] = v.w;
    }

    const int ty = tid >> 4, tx = tid & 15;
    const int i0 = ty*4, j0 = tx*4, cc0 = tx*8;
    const int grow = tid >> 2, lane = tid & 3;

    // O accumulators: [i][cp] pairs over the 8 c-columns
    ull o2[4][4];
#pragma unroll
    for (int i = 0; i < 4; i++)
#pragma unroll
        for (int q = 0; q < 4; q++) o2[i][q] = 0ull;
    float m_run = -1e30f, l_run = 0.f;
    const float scale = 0.08838834764831845f;  // 1/sqrt(128)

    for (int kb = 0; kb < LROW; kb += 64) {
#pragma unroll
        for (int t = 0; t < 8; t++) {
            int id = tid + t*256;
            int j = id >> 5, cq = (id & 31)*4;
            float4 v = *(const float4*)(php + (size_t)(kb + j)*stride + cq);
            Ks[(cq+0)*68 + j] = v.x; Ks[(cq+1)*68 + j] = v.y;
            Ks[(cq+2)*68 + j] = v.z; Ks[(cq+3)*68 + j] = v.w;
        }
#pragma unroll
        for (int t = 0; t < 8; t++) {
            int id = tid + t*256;
            int j = id >> 5, cq = (id & 31)*4;
            *(float4*)&Vs[j*132 + cq] = *(const float4*)(gp + (size_t)(kb + j)*stride + cq);
        }
        __syncthreads();

        // S[64][64] = Q K^T * scale  (pairs over j)
        ull s2[4][2];
#pragma unroll
        for (int i = 0; i < 4; i++) { s2[i][0] = 0ull; s2[i][1] = 0ull; }
#pragma unroll 8
        for (int c = 0; c < CDIM; c++) {
            float4 q4 = *(const float4*)&Qs[c*68 + i0];
            float aq[4] = {q4.x, q4.y, q4.z, q4.w};
            longlong2 kk2 = *(const longlong2*)&Ks[c*68 + j0];
            ull k2[2] = {(ull)kk2.x, (ull)kk2.y};
#pragma unroll
            for (int i = 0; i < 4; i++) {
                ull ad = pack2(aq[i], aq[i]);
                s2[i][0] = ffma2(ad, k2[0], s2[i][0]);
                s2[i][1] = ffma2(ad, k2[1], s2[i][1]);
            }
        }
#pragma unroll
        for (int i = 0; i < 4; i++) {
            float2 p0f = unpack2(s2[i][0]);
            float2 p1f = unpack2(s2[i][1]);
            float4 pv = make_float4(p0f.x*scale, p0f.y*scale, p1f.x*scale, p1f.y*scale);
            *(float4*)&Ps[(i0 + i)*68 + j0] = pv;
        }
        __syncthreads();

        // online softmax per row (4 threads/row)
        float mx = -1e30f;
#pragma unroll
        for (int jj = 0; jj < 16; jj++)
            mx = fmaxf(mx, Ps[grow*68 + jj*4 + lane]);
        mx = fmaxf(mx, __shfl_xor_sync(0xffffffffu, mx, 1));
        mx = fmaxf(mx, __shfl_xor_sync(0xffffffffu, mx, 2));
        float m_new = fmaxf(m_run, mx);
        float alpha = __expf(m_run - m_new);
        float ssum = 0.f;
#pragma unroll
        for (int jj = 0; jj < 16; jj++) {
            int idx = grow*68 + jj*4 + lane;
            float e = __expf(Ps[idx] - m_new);
            Ps[idx] = e;
            ssum += e;
        }
        ssum += __shfl_xor_sync(0xffffffffu, ssum, 1);
        ssum += __shfl_xor_sync(0xffffffffu, ssum, 2);
        l_run = l_run * alpha + ssum;
        m_run = m_new;
        if (lane == 0) red_alpha[grow] = alpha;
        __syncthreads();

        // O = O*alpha + P V  (pairs over c-columns)
#pragma unroll
        for (int i = 0; i < 4; i++) {
            float al = red_alpha[i0 + i];
            ull ap = pack2(al, al);
#pragma unroll
            for (int q = 0; q < 4; q++) o2[i][q] = fmul2(o2[i][q], ap);
        }
#pragma unroll 4
        for (int j = 0; j < 64; j++) {
            longlong2 v0 = *(const longlong2*)&Vs[j*132 + cc0];
            longlong2 v1 = *(const longlong2*)&Vs[j*132 + cc0 + 4];
            ull vv[4] = {(ull)v0.x, (ull)v0.y, (ull)v1.x, (ull)v1.y};
            float pp[4];
#pragma unroll
            for (int i = 0; i < 4; i++) pp[i] = Ps[(i0 + i)*68 + j];
#pragma unroll
            for (int i = 0; i < 4; i++) {
                ull pd = pack2(pp[i], pp[i]);
#pragma unroll
                for (int q = 0; q < 4; q++)
                    o2[i][q] = ffma2(pd, vv[q], o2[i][q]);
            }
        }
        __syncthreads();
    }

    if (lane == 0) red_l[grow] = l_run;
    __syncthreads();
#pragma unroll
    for (int i = 0; i < 4; i++) {
        float inv = 1.f / red_l[i0 + i];
        ull ip = pack2(inv, inv);
        float2 r0f = unpack2(fmul2(o2[i][0], ip));
        float2 r1f = unpack2(fmul2(o2[i][1], ip));
        float2 r2f = unpack2(fmul2(o2[i][2], ip));
        float2 r3f = unpack2(fmul2(o2[i][3], ip));
        float* dst = outp + (size_t)(q0 + i0 + i)*stride + cc0;
        *(float4*)dst       = make_float4(r0f.x, r0f.y, r1f.x, r1f.y);
        *(float4*)(dst + 4) = make_float4(r2f.x, r2f.y, r3f.x, r3f.y);
    }
}

// ---------------- NHWC -> NCHW output transpose ----------------
__global__ void transpose_out(float* __restrict__ out) {
    __shared__ float tile[32][33];
    int n = blockIdx.z;
    int hw0 = blockIdx.x * 32;
    int c0 = blockIdx.y * 32;
    int tx = threadIdx.x, ty = threadIdx.y;
    const float* src = g_g + (size_t)n*HWD*CDIM;
#pragma unroll
    for (int i = 0; i < 32; i += 8)
        tile[ty + i][tx] = src[(size_t)(hw0 + ty + i)*CDIM + c0 + tx];
    __syncthreads();
    float* dst = out + (size_t)n*CDIM*HWD;
#pragma unroll
    for (int i = 0; i < 32; i += 8)
        dst[(size_t)(c0 + ty + i)*HWD + hw0 + tx] = tile[tx][ty + i];
}

// ---------------- launch ----------------
extern "C" void kernel_launch(void* const* d_in, const int* in_sizes, int n_in,
                              void* d_out, int out_size) {
    const float* f  = (const float*)d_in[0];
    const float* W7 = (const float*)d_in[1];
    const float* m7 = (const float*)d_in[2];
    const float* v7 = (const float*)d_in[3];
    const float* b7 = (const float*)d_in[4];
    const float* Wa = (const float*)d_in[5];
    const float* ma = (const float*)d_in[6];
    const float* va = (const float*)d_in[7];
    const float* ba = (const float*)d_in[8];
    float* out = (float*)d_out;

    prep_kernel<<<64, 256>>>(W7, m7, v7, b7, Wa, ma, va, ba);

    // stage A: theta, phi, g, sc_h, sc_v
    gemm_kernel<0><<<dim3(PTOT/128, 5), 256>>>(f);

    // axial attention, both directions
    int smem_bytes = (128*68 + 128*68 + 64*132 + 64*68 + 128) * 4;
    cudaFuncSetAttribute(attn_kernel, cudaFuncAttributeMaxDynamicSharedMemorySize, smem_bytes);
    attn_kernel<<<dim3(LROW/64, NROWS, 2), 256, smem_bytes>>>();

    // C1: u = relu(ah*W3 + b3 + sc_h) -> g_th ; v = relu(av*W5 + b5 + sc_v) -> g_ph
    gemm_kernel<1><<<dim3(PTOT/128, 2), 256>>>(nullptr);

    // C2: final conv over concat(u, v) -> g_g (NHWC tmp)
    gemm_kernel<2><<<dim3(PTOT/128, 1), 256>>>(nullptr);

    // NHWC -> NCHW
    transpose_out<<<dim3(HWD/32, CDIM/32, NB), dim3(32, 8)>>>(out);
}